// round 17
// baseline (speedup 1.0000x reference)
#include <cuda_runtime.h>
#include <math.h>
#include <stdint.h>

#define HX_B 16
#define HX_C 256
#define HX_H 128
#define HX_W 128
#define HX_HW (HX_H * HX_W)      // 16384
#define HX_HW4 (HX_HW / 4)       // 4096

#define GRID 128                 // 4096 quads / 32 per block; all co-resident
#define QPB 32                   // pixel-quads per block
#define SLICES 16                // channel slices (one per warp-ish group)
#define CPT 16                   // channels per thread (16 float4 in regs)

// scratch (device globals: allocation-free per harness rules)
__device__ float    g_avg[HX_B * HX_HW];
__device__ float    g_max[HX_B * HX_HW];
__device__ unsigned g_tick;      // monotonic grid-barrier ticket (never reset)

// ---------------------------------------------------------------------------
// Grid barrier: monotonic ticket — replay-safe without reset. All GRID
// blocks co-resident (GRID=128 < 148 SMs, 1 block/SM).
// ---------------------------------------------------------------------------
__device__ __forceinline__ void grid_bar() {
    __syncthreads();
    if (threadIdx.x == 0) {
        __threadfence();                       // publish avg/max writes
        unsigned t = atomicAdd(&g_tick, 1u);
        unsigned target = (t / GRID + 1u) * GRID;
        unsigned v;
        for (;;) {
            asm volatile("ld.acquire.gpu.u32 %0, [%1];" : "=r"(v) : "l"(&g_tick));
            if (v >= target) break;
            __nanosleep(32);
        }
    }
    __syncthreads();
}

__device__ __forceinline__ float ld_plane(const float* __restrict__ y, int h, int w) {
    return (h >= 0 && h < HX_H && w >= 0 && w < HX_W) ? __ldg(y + h * HX_W + w) : 0.f;
}

// ---------------------------------------------------------------------------
// Persistent fused kernel. Per chunk (= 1 batch): 16 LDG.128/thread into
// REGISTERS -> in-register reduce -> smem combine -> grid barrier -> stencil
// -> multiply regs, STG.128. x crosses LTS exactly once; chunk k's stores
// drain while chunk k+1's loads issue (no buffering needed).
// ---------------------------------------------------------------------------
__global__ void __launch_bounds__(512)
fused_kernel(const float4* __restrict__ x4,
             float4* __restrict__ o4,
             const float* __restrict__ wts) {
    __shared__ float4 s_sum[SLICES][QPB];            // 8 KiB
    __shared__ float4 s_mx[SLICES][QPB];             // 8 KiB
    __shared__ __align__(16) float s_fac[QPB * 4];   // 512 B

    const int tid = threadIdx.x;
    const int q   = tid & (QPB - 1);      // 0..31  (warp lanes = consecutive q)
    const int s   = tid >> 5;             // 0..15  channel slice
    const int G0  = blockIdx.x * QPB;
    const int qb  = G0 + q;               // quad within plane, 0..4095

    float4* av4 = reinterpret_cast<float4*>(g_avg);
    float4* mx4 = reinterpret_cast<float4*>(g_max);

    for (int ch = 0; ch < HX_B; ch++) {
        const size_t base = ((size_t)(ch * HX_C + s * CPT)) * HX_HW4 + qb;
        const float4* px = x4 + base;

        // ---- load 16 float4 into registers (MLP=16, evict-first) ----
        float4 v[CPT];
        #pragma unroll
        for (int c = 0; c < CPT; c++)
            v[c] = __ldcs(px + (size_t)c * HX_HW4);

        // ---- in-register reduce over this thread's 16 channels ----
        float4 sum = v[0];
        float4 mx  = v[0];
        #pragma unroll
        for (int c = 1; c < CPT; c++) {
            sum.x += v[c].x; sum.y += v[c].y; sum.z += v[c].z; sum.w += v[c].w;
            mx.x = fmaxf(mx.x, v[c].x); mx.y = fmaxf(mx.y, v[c].y);
            mx.z = fmaxf(mx.z, v[c].z); mx.w = fmaxf(mx.w, v[c].w);
        }
        s_sum[s][q] = sum;
        s_mx[s][q]  = mx;
        __syncthreads();

        // ---- combine 16 slices (one warp), write avg/max planes ----
        if (tid < QPB) {
            float4 a = s_sum[0][tid];
            float4 m = s_mx[0][tid];
            #pragma unroll
            for (int k = 1; k < SLICES; k++) {
                float4 a2 = s_sum[k][tid];
                float4 m2 = s_mx[k][tid];
                a.x += a2.x; a.y += a2.y; a.z += a2.z; a.w += a2.w;
                m.x = fmaxf(m.x, m2.x); m.y = fmaxf(m.y, m2.y);
                m.z = fmaxf(m.z, m2.z); m.w = fmaxf(m.w, m2.w);
            }
            const float inv = 1.0f / HX_C;
            a.x *= inv; a.y *= inv; a.z *= inv; a.w *= inv;
            av4[ch * HX_HW4 + G0 + tid] = a;
            mx4[ch * HX_HW4 + G0 + tid] = m;
        }

        grid_bar();                        // whole plane's avg/max visible

        // ---- stencil + sigmoid: one sub-pixel per thread (128 threads) ----
        if (tid < QPB * 4) {
            const int qq  = tid >> 2;
            const int sub = tid & 3;
            const int qg  = G0 + qq;
            const int h   = qg >> 5;
            const int w   = (qg & 31) * 4 + sub;
            float acc = 0.f;
            #pragma unroll
            for (int m = 0; m < 2; m++) {
                const float* y = (m == 0 ? g_avg : g_max) + ch * HX_HW;
                float p0 = __ldg(wts + ch * 8 + m * 4 + 0);
                float p1 = __ldg(wts + ch * 8 + m * 4 + 1);
                float p2 = __ldg(wts + ch * 8 + m * 4 + 2);
                float p3 = __ldg(wts + ch * 8 + m * 4 + 3);
                float pc = -(p0 + p1 + p2 + p3);
                acc += p0 * ld_plane(y, h - 1, w)
                     + p1 * ld_plane(y, h + 1, w)
                     + p2 * ld_plane(y, h, w - 1)
                     + p3 * ld_plane(y, h, w + 1)
                     + pc * ld_plane(y, h, w);
            }
            s_fac[tid] = 1.0f + 1.0f / (1.0f + __expf(-acc));
        }
        __syncthreads();

        // ---- multiply registers, stream out (fire-and-forget stores) ----
        const float4 f = reinterpret_cast<const float4*>(s_fac)[q];
        float4* po = o4 + base;
        #pragma unroll
        for (int c = 0; c < CPT; c++) {
            float4 o;
            o.x = v[c].x * f.x; o.y = v[c].y * f.y;
            o.z = v[c].z * f.z; o.w = v[c].w * f.w;
            __stcs(po + (size_t)c * HX_HW4, o);
        }
        // no extra sync: s_sum rewrite next iter is fenced by this iter's
        // grid_bar (combine-reads happened before it); s_fac rewrite is
        // fenced by next iter's grid_bar + __syncthreads.
    }
}

extern "C" void kernel_launch(void* const* d_in, const int* in_sizes, int n_in,
                              void* d_out, int out_size) {
    const float4* x4  = (const float4*)d_in[0];
    const float*  wts = (const float*)d_in[1];
    float4*       o4  = (float4*)d_out;
    fused_kernel<<<GRID, 512>>>(x4, o4, wts);
}